// round 15
// baseline (speedup 1.0000x reference)
#include <cuda_runtime.h>
#include <mma.h>
#include <cuda_fp16.h>
#include <cstdint>
#include <math.h>

using namespace nvcuda;

#define SEQ 8192
#define DIM 768
#define QV2 (2 * DIM)   // 1536: packed [q' | v] columns

// ---------------- scratch (static device arrays; no allocs) ----------------
__device__ __align__(128) __half g_Xh  [(size_t)SEQ * DIM];
__device__ __align__(128) __half g_Wc2 [(size_t)QV2 * DIM];       // rows: [N | wv]
__device__ __align__(128) __half g_QVh [(size_t)SEQ * QV2];       // [q' | v] cols
__device__ __align__(128) __half g_P   [(size_t)SEQ * SEQ];       // exp2(s'), unnormalized
__device__ __align__(128) float  g_RS  [(size_t)SEQ * 64];        // per-block row partials
__device__ __align__(128) float  g_Part[(size_t)3 * SEQ * DIM];   // PV split-K partials

// ---------------- helpers ----------------
__device__ __forceinline__ uint32_t smem_u32(const void* p) {
    uint32_t a;
    asm("{ .reg .u64 t; cvta.to.shared.u64 t, %1; cvt.u32.u64 %0, t; }" : "=r"(a) : "l"(p));
    return a;
}
__device__ __forceinline__ void cp_async16(uint32_t dst, const void* src) {
    asm volatile("cp.async.cg.shared.global [%0], [%1], 16;" :: "r"(dst), "l"(src) : "memory");
}
#define CP_COMMIT() asm volatile("cp.async.commit_group;" ::: "memory")
#define CP_WAIT1()  asm volatile("cp.async.wait_group 1;" ::: "memory")
#define CP_WAIT0()  asm volatile("cp.async.wait_group 0;" ::: "memory")

// ---------------------------------------------------------------------------
// GEMM (fp16 in, fp32 acc) — proven core.
// BM=BN=128, BK=64, 256 thr = 8 warps (2m x 4n), warp tile 64x32.
// 3-stage cp.async, launch_bounds(256,2).
//   BT=true  (NT): C = A[M,K] @ B[N,K]^T     BT=false (NN): C = A[M,K] @ B[K,N]
// Split-K via blockIdx.z (EPI=0 only). EPI: 0=fp32 store, 1=fp16 staged,
// 2=exp2 on acc regs + fp16 staged + 2-phase smem partial row sums into RS.
// ---------------------------------------------------------------------------
constexpr int BM = 128, BN = 128, BK = 64;
constexpr int LDA = 72;
constexpr int STG_A = BM * LDA;

template <int EPI, bool BT>
__global__ __launch_bounds__(256, 2) void gemm_h(
    const __half* __restrict__ A, int lda,
    const __half* __restrict__ B, int ldb,
    void* __restrict__ Cv, int ldc,
    int kTot, int splitIters, size_t planeStride,
    float* __restrict__ RS)
{
    constexpr int LDB   = BT ? 72 : 136;
    constexpr int STG_B = BT ? BN * 72 : BK * 136;

    extern __shared__ __half smh[];
    __half* As = smh;
    __half* Bs = smh + 3 * STG_A;

    const int tid  = threadIdx.x;
    const int warp = tid >> 5;
    const int bm   = blockIdx.y * BM;
    const int bn   = blockIdx.x * BN;
    const int wm   = (warp & 1) * 64;
    const int wn   = (warp >> 1) * 32;

    const int z    = blockIdx.z;
    const int kit0 = z * splitIters;
    const int nit  = min(splitIters, kTot - kit0);

    const uint32_t sA = smem_u32(As);
    const uint32_t sB = smem_u32(Bs);

    auto load_tile = [&](int b, int it) {
        const int k0 = (kit0 + it) * BK;
        const uint32_t dA = sA + (uint32_t)(b * STG_A) * 2;
        #pragma unroll
        for (int t = 0; t < 4; t++) {
            int g = tid + t * 256;
            int r = g >> 3, c = (g & 7) << 3;
            cp_async16(dA + (uint32_t)(r * LDA + c) * 2,
                       A + (size_t)(bm + r) * lda + k0 + c);
        }
        const uint32_t dB = sB + (uint32_t)(b * STG_B) * 2;
        if constexpr (BT) {
            #pragma unroll
            for (int t = 0; t < 4; t++) {
                int g = tid + t * 256;
                int r = g >> 3, c = (g & 7) << 3;
                cp_async16(dB + (uint32_t)(r * LDB + c) * 2,
                           B + (size_t)(bn + r) * ldb + k0 + c);
            }
        } else {
            #pragma unroll
            for (int t = 0; t < 4; t++) {
                int g = tid + t * 256;
                int r = g >> 4, c = (g & 15) << 3;
                cp_async16(dB + (uint32_t)(r * LDB + c) * 2,
                           B + (size_t)(k0 + r) * ldb + bn + c);
            }
        }
        CP_COMMIT();
    };

    wmma::fragment<wmma::accumulator, 16, 16, 16, float> acc[4][2];
    #pragma unroll
    for (int mi = 0; mi < 4; mi++)
        #pragma unroll
        for (int ni = 0; ni < 2; ni++)
            wmma::fill_fragment(acc[mi][ni], 0.0f);

    load_tile(0, 0);
    load_tile(1, 1);

    #pragma unroll 3
    for (int i = 0; i < nit; i++) {
        if (i + 1 < nit) { CP_WAIT1(); } else { CP_WAIT0(); }
        __syncthreads();
        if (i + 2 < nit) load_tile((i + 2) % 3, i + 2);

        const int s = i % 3;
        const __half* Ab = As + s * STG_A;
        const __half* Bb = Bs + s * STG_B;

        #pragma unroll
        for (int kk = 0; kk < BK; kk += 16) {
            wmma::fragment<wmma::matrix_a, 16, 16, 16, __half, wmma::row_major> af[4];
            #pragma unroll
            for (int mi = 0; mi < 4; mi++)
                wmma::load_matrix_sync(af[mi], Ab + (wm + mi * 16) * LDA + kk, LDA);

            if constexpr (BT) {
                wmma::fragment<wmma::matrix_b, 16, 16, 16, __half, wmma::col_major> bf[2];
                #pragma unroll
                for (int ni = 0; ni < 2; ni++)
                    wmma::load_matrix_sync(bf[ni], Bb + (wn + ni * 16) * LDB + kk, LDB);
                #pragma unroll
                for (int mi = 0; mi < 4; mi++)
                    #pragma unroll
                    for (int ni = 0; ni < 2; ni++)
                        wmma::mma_sync(acc[mi][ni], af[mi], bf[ni], acc[mi][ni]);
            } else {
                wmma::fragment<wmma::matrix_b, 16, 16, 16, __half, wmma::row_major> bf[2];
                #pragma unroll
                for (int ni = 0; ni < 2; ni++)
                    wmma::load_matrix_sync(bf[ni], Bb + kk * LDB + wn + ni * 16, LDB);
                #pragma unroll
                for (int mi = 0; mi < 4; mi++)
                    #pragma unroll
                    for (int ni = 0; ni < 2; ni++)
                        wmma::mma_sync(acc[mi][ni], af[mi], bf[ni], acc[mi][ni]);
            }
        }
    }

    if constexpr (EPI == 0) {
        float* C = (float*)Cv + (size_t)z * planeStride;
        #pragma unroll
        for (int mi = 0; mi < 4; mi++)
            #pragma unroll
            for (int ni = 0; ni < 2; ni++)
                wmma::store_matrix_sync(
                    C + (size_t)(bm + wm + mi * 16) * ldc + bn + wn + ni * 16,
                    acc[mi][ni], ldc, wmma::mem_row_major);
    } else {
        constexpr int LDC_S = 132;                       // floats
        float* Cs  = (float*)smh;                        // 67584 B
        float* red = (float*)((char*)smh + 68608);       // 128*33*4 = 16896 B
        __syncthreads();
        #pragma unroll
        for (int mi = 0; mi < 4; mi++) {
            #pragma unroll
            for (int ni = 0; ni < 2; ni++) {
                if constexpr (EPI == 2) {
                    #pragma unroll
                    for (int e = 0; e < acc[mi][ni].num_elements; e++)
                        acc[mi][ni].x[e] = exp2f(acc[mi][ni].x[e]);
                }
                wmma::store_matrix_sync(Cs + (wm + mi * 16) * LDC_S + wn + ni * 16,
                                        acc[mi][ni], LDC_S, wmma::mem_row_major);
            }
        }
        __syncthreads();
        __half* C = (__half*)Cv;
        const int lane = tid & 31;
        #pragma unroll
        for (int t = 0; t < 16; t++) {
            // r = warp + 8t, c = lane*4 (constant column chunk per thread)
            int g = tid + t * 256;
            int r = g >> 5, c = (g & 31) << 2;
            float4 v = *reinterpret_cast<const float4*>(Cs + r * LDC_S + c);
            if constexpr (EPI == 2)
                red[r * 33 + lane] = v.x + v.y + v.z + v.w;   // 4-col partial
            __half2 h0 = __floats2half2_rn(v.x, v.y);
            __half2 h1 = __floats2half2_rn(v.z, v.w);
            uint2 u;
            u.x = *reinterpret_cast<uint32_t*>(&h0);
            u.y = *reinterpret_cast<uint32_t*>(&h1);
            *reinterpret_cast<uint2*>(C + (size_t)(bm + r) * ldc + bn + c) = u;
        }
        if constexpr (EPI == 2) {
            __syncthreads();
            if (tid < 128) {                             // 32 conflict-free scalar LDS
                const float* pr = red + tid * 33;
                float s = 0.0f;
                #pragma unroll
                for (int j = 0; j < 32; j++) s += pr[j];
                RS[(size_t)(bm + tid) * gridDim.x + blockIdx.x] = s;
            }
        }
    }
}

// ---------------------------------------------------------------------------
// N = alpha * Wk^T @ Wq  (TN, fp32 in, fp32 acc, fp16 out), 768x768.
// (alpha includes log2e so the score epilogue can use exp2.)
// Block 64x64, 128 thr = 4 warps (2x2), warp tile 32x32.
// ---------------------------------------------------------------------------
__global__ __launch_bounds__(128) void wkwq_tn(
    const float* __restrict__ wk, const float* __restrict__ wq,
    __half* __restrict__ Nout, float alpha)
{
    __shared__ __half Ta[64 * 72];     // [m][j]
    __shared__ __half Tb[64 * 72];     // [m][k]
    __shared__ float  Cs[64 * 68];

    const int tid  = threadIdx.x;
    const int warp = tid >> 5;
    const int j0   = blockIdx.y * 64;
    const int k0   = blockIdx.x * 64;
    const int wj   = (warp & 1) * 32;
    const int wk_  = (warp >> 1) * 32;

    wmma::fragment<wmma::accumulator, 16, 16, 16, float> acc[2][2];
    #pragma unroll
    for (int mi = 0; mi < 2; mi++)
        #pragma unroll
        for (int ni = 0; ni < 2; ni++)
            wmma::fill_fragment(acc[mi][ni], 0.0f);

    for (int m0 = 0; m0 < DIM; m0 += 64) {
        __syncthreads();
        #pragma unroll
        for (int e = 0; e < 8; e++) {
            int g = tid + e * 128;
            int r = g >> 4, c = (g & 15) << 2;
            float4 va = *reinterpret_cast<const float4*>(
                wk + (size_t)(m0 + r) * DIM + j0 + c);
            float4 vb = *reinterpret_cast<const float4*>(
                wq + (size_t)(m0 + r) * DIM + k0 + c);
            __half2 a0 = __floats2half2_rn(va.x, va.y);
            __half2 a1 = __floats2half2_rn(va.z, va.w);
            __half2 b0 = __floats2half2_rn(vb.x, vb.y);
            __half2 b1 = __floats2half2_rn(vb.z, vb.w);
            uint2 ua, ub;
            ua.x = *reinterpret_cast<uint32_t*>(&a0);
            ua.y = *reinterpret_cast<uint32_t*>(&a1);
            ub.x = *reinterpret_cast<uint32_t*>(&b0);
            ub.y = *reinterpret_cast<uint32_t*>(&b1);
            *reinterpret_cast<uint2*>(&Ta[r * 72 + c]) = ua;
            *reinterpret_cast<uint2*>(&Tb[r * 72 + c]) = ub;
        }
        __syncthreads();

        #pragma unroll
        for (int kk = 0; kk < 64; kk += 16) {
            wmma::fragment<wmma::matrix_a, 16, 16, 16, __half, wmma::col_major> af[2];
            wmma::fragment<wmma::matrix_b, 16, 16, 16, __half, wmma::row_major> bf[2];
            #pragma unroll
            for (int i = 0; i < 2; i++)
                wmma::load_matrix_sync(af[i], &Ta[kk * 72 + wj + i * 16], 72);
            #pragma unroll
            for (int i = 0; i < 2; i++)
                wmma::load_matrix_sync(bf[i], &Tb[kk * 72 + wk_ + i * 16], 72);
            #pragma unroll
            for (int mi = 0; mi < 2; mi++)
                #pragma unroll
                for (int ni = 0; ni < 2; ni++)
                    wmma::mma_sync(acc[mi][ni], af[mi], bf[ni], acc[mi][ni]);
        }
    }

    __syncthreads();
    #pragma unroll
    for (int mi = 0; mi < 2; mi++) {
        #pragma unroll
        for (int ni = 0; ni < 2; ni++) {
            #pragma unroll
            for (int e = 0; e < acc[mi][ni].num_elements; e++)
                acc[mi][ni].x[e] *= alpha;
            wmma::store_matrix_sync(Cs + (wj + mi * 16) * 68 + wk_ + ni * 16,
                                    acc[mi][ni], 68, wmma::mem_row_major);
        }
    }
    __syncthreads();
    #pragma unroll
    for (int e = 0; e < 8; e++) {
        int g = tid + e * 128;
        int r = g >> 4, c = (g & 15) << 2;
        float4 v = *reinterpret_cast<const float4*>(&Cs[r * 68 + c]);
        __half2 h0 = __floats2half2_rn(v.x, v.y);
        __half2 h1 = __floats2half2_rn(v.z, v.w);
        uint2 u;
        u.x = *reinterpret_cast<uint32_t*>(&h0);
        u.y = *reinterpret_cast<uint32_t*>(&h1);
        *reinterpret_cast<uint2*>(&Nout[(size_t)(j0 + r) * DIM + k0 + c]) = u;
    }
}

// ---------------- fused fp32 -> fp16 conversion (x, wv) ----------------
__global__ void __launch_bounds__(256) f2h_all(
    const float* __restrict__ x, const float* __restrict__ wv,
    __half* __restrict__ Xh, __half* __restrict__ Wv_dst)
{
    constexpr int NX = SEQ * DIM / 4;
    constexpr int NW = DIM * DIM / 4;
    int i = blockIdx.x * 256 + threadIdx.x;
    const float* src; __half* dst; int j;
    if (i < NX)           { src = x;  dst = Xh;     j = i; }
    else if (i < NX + NW) { src = wv; dst = Wv_dst; j = i - NX; }
    else return;
    float4 v = reinterpret_cast<const float4*>(src)[j];
    __half2 h0 = __floats2half2_rn(v.x, v.y);
    __half2 h1 = __floats2half2_rn(v.z, v.w);
    uint2 u;
    u.x = *reinterpret_cast<uint32_t*>(&h0);
    u.y = *reinterpret_cast<uint32_t*>(&h1);
    reinterpret_cast<uint2*>(dst)[j] = u;
}

// ---------------- fused: invL from RS partials + split-K reduce + normalize ----
__global__ void __launch_bounds__(256) reduce_norm_all(
    const float* __restrict__ part, const float* __restrict__ RS,
    float* __restrict__ out)
{
    constexpr int PLANE4 = SEQ * DIM / 4;
    __shared__ float sinv[8];

    const int row0 = blockIdx.x * 8;
    const int w    = threadIdx.x >> 5;
    const int lane = threadIdx.x & 31;

    const float* rs = RS + (size_t)(row0 + w) * 64;
    float s = rs[lane] + rs[lane + 32];
    #pragma unroll
    for (int off = 16; off > 0; off >>= 1)
        s += __shfl_down_sync(0xFFFFFFFF, s, off);
    if (lane == 0) sinv[w] = 1.0f / s;
    __syncthreads();

    const float4* p = reinterpret_cast<const float4*>(part);
    float4* o = reinterpret_cast<float4*>(out);
    #pragma unroll
    for (int k = 0; k < 6; k++) {
        int i = threadIdx.x + k * 256;
        int r = i / 192;
        size_t idx = (size_t)(row0) * 192 + i;
        const float sv = sinv[r];
        float4 a = p[idx];
        float4 b = p[idx + PLANE4];
        float4 c = p[idx + 2 * PLANE4];
        float4 v;
        v.x = (a.x + b.x + c.x) * sv;
        v.y = (a.y + b.y + c.y) * sv;
        v.z = (a.z + b.z + c.z) * sv;
        v.w = (a.w + b.w + c.w) * sv;
        o[idx] = v;
    }
}

// ---------------- launch ----------------
extern "C" void kernel_launch(void* const* d_in, const int* in_sizes, int n_in,
                              void* d_out, int out_size)
{
    const float* x  = (const float*)d_in[0];
    const float* wq = (const float*)d_in[1];
    const float* wk = (const float*)d_in[2];
    const float* wv = (const float*)d_in[3];
    float* out = (float*)d_out;

    __half *Xh, *Wc2, *QVh, *P;
    float *RS, *Part;
    cudaGetSymbolAddress((void**)&Xh,  g_Xh);
    cudaGetSymbolAddress((void**)&Wc2, g_Wc2);
    cudaGetSymbolAddress((void**)&QVh, g_QVh);
    cudaGetSymbolAddress((void**)&P,   g_P);
    cudaGetSymbolAddress((void**)&RS,  g_RS);
    cudaGetSymbolAddress((void**)&Part, g_Part);

    constexpr int SM_NT = 3 * (STG_A + BN * 72) * 2;    // 110592
    constexpr int SM_NN = 3 * (STG_A + BK * 136) * 2;   // 107520
    cudaFuncSetAttribute((const void*)gemm_h<1, true>,
                         cudaFuncAttributeMaxDynamicSharedMemorySize, SM_NT);
    cudaFuncSetAttribute((const void*)gemm_h<2, true>,
                         cudaFuncAttributeMaxDynamicSharedMemorySize, SM_NT);
    cudaFuncSetAttribute((const void*)gemm_h<0, false>,
                         cudaFuncAttributeMaxDynamicSharedMemorySize, SM_NN);

    dim3 blk(256);
    const float alpha = 1.44269504088896f / sqrtf((float)DIM);   // log2e folded

    // (1) fp32 -> fp16 for x; wv -> Wc2 rows [768,1536)
    constexpr int N4 = (SEQ * DIM + DIM * DIM) / 4;
    f2h_all<<<(N4 + 255) / 256, 256>>>(x, wv, Xh, Wc2 + (size_t)DIM * DIM);

    // (2) N = (alpha*log2e) * Wk^T @ Wq -> Wc2 rows [0,768)
    wkwq_tn<<<dim3(DIM / 64, DIM / 64), 128>>>(wk, wq, Wc2, alpha);

    // (3) projection (NT): QV = Xh @ Wc2^T -> [q' | v], fp16
    dim3 gProj(QV2 / BN, SEQ / BM);                  // 12 x 64
    gemm_h<1, true><<<gProj, blk, SM_NT>>>(
        Xh, DIM, Wc2, DIM, QVh, QV2, DIM / BK, DIM / BK, 0, nullptr);

    // (4) P = exp2(Q' @ Xh^T) (NT), fp16, + smem-partial row sums
    dim3 gScore(SEQ / BN, SEQ / BM);                 // 64 x 64
    gemm_h<2, true><<<gScore, blk, SM_NT>>>(
        QVh, QV2, Xh, DIM, P, SEQ, DIM / BK, DIM / BK, 0, RS);

    // (5) PV (NN, B = V slice of QVh) split-K=3 partials
    dim3 gPV(DIM / BN, SEQ / BM, 3);                 // 6 x 64 x 3
    gemm_h<0, false><<<gPV, blk, SM_NN>>>(
        P, SEQ, QVh + DIM, QV2, Part, DIM, SEQ / BK, 43,
        (size_t)SEQ * DIM, nullptr);

    // (6) out = (sum of split-K partials) / rowsum
    reduce_norm_all<<<SEQ / 8, 256>>>(Part, RS, out);
}

// round 16
// speedup vs baseline: 1.5333x; 1.5333x over previous
#include <cuda_runtime.h>
#include <mma.h>
#include <cuda_fp16.h>
#include <cstdint>
#include <math.h>

using namespace nvcuda;

#define SEQ 8192
#define DIM 768
#define QV2 (2 * DIM)   // 1536: packed [q' | v] columns

// ---------------- scratch (static device arrays; no allocs) ----------------
__device__ __align__(128) __half g_Xh  [(size_t)SEQ * DIM];
__device__ __align__(128) __half g_Wc2 [(size_t)QV2 * DIM];       // rows: [N | wv]
__device__ __align__(128) __half g_QVh [(size_t)SEQ * QV2];       // [q' | v] cols
__device__ __align__(128) __half g_P   [(size_t)SEQ * SEQ];       // exp2(s'), unnormalized
__device__ __align__(128) float  g_RS  [(size_t)SEQ * 64];        // per-block row partials
__device__ __align__(128) float  g_Part[(size_t)3 * SEQ * DIM];   // PV split-K partials

// ---------------- helpers ----------------
__device__ __forceinline__ uint32_t smem_u32(const void* p) {
    uint32_t a;
    asm("{ .reg .u64 t; cvta.to.shared.u64 t, %1; cvt.u32.u64 %0, t; }" : "=r"(a) : "l"(p));
    return a;
}
__device__ __forceinline__ void cp_async16(uint32_t dst, const void* src) {
    asm volatile("cp.async.cg.shared.global [%0], [%1], 16;" :: "r"(dst), "l"(src) : "memory");
}
#define CP_COMMIT() asm volatile("cp.async.commit_group;" ::: "memory")
#define CP_WAIT1()  asm volatile("cp.async.wait_group 1;" ::: "memory")
#define CP_WAIT0()  asm volatile("cp.async.wait_group 0;" ::: "memory")

// ---------------------------------------------------------------------------
// GEMM (fp16 in, fp32 acc) — proven R13 core/epilogue.
// BM=BN=128, BK=64, 256 thr = 8 warps (2m x 4n), warp tile 64x32.
// 3-stage cp.async, launch_bounds(256,2).
//   BT=true  (NT): C = A[M,K] @ B[N,K]^T     BT=false (NN): C = A[M,K] @ B[K,N]
// Split-K via blockIdx.z (EPI=0 only). EPI: 0=fp32 store, 1=fp16 staged,
// 2=exp2 on acc regs + fp16 staged + per-block row sums (smem re-read) into RS.
// ---------------------------------------------------------------------------
constexpr int BM = 128, BN = 128, BK = 64;
constexpr int LDA = 72;
constexpr int STG_A = BM * LDA;

template <int EPI, bool BT>
__global__ __launch_bounds__(256, 2) void gemm_h(
    const __half* __restrict__ A, int lda,
    const __half* __restrict__ B, int ldb,
    void* __restrict__ Cv, int ldc,
    int kTot, int splitIters, size_t planeStride,
    float* __restrict__ RS)
{
    constexpr int LDB   = BT ? 72 : 136;
    constexpr int STG_B = BT ? BN * 72 : BK * 136;

    extern __shared__ __half smh[];
    __half* As = smh;
    __half* Bs = smh + 3 * STG_A;

    const int tid  = threadIdx.x;
    const int warp = tid >> 5;
    const int bm   = blockIdx.y * BM;
    const int bn   = blockIdx.x * BN;
    const int wm   = (warp & 1) * 64;
    const int wn   = (warp >> 1) * 32;

    const int z    = blockIdx.z;
    const int kit0 = z * splitIters;
    const int nit  = min(splitIters, kTot - kit0);

    const uint32_t sA = smem_u32(As);
    const uint32_t sB = smem_u32(Bs);

    auto load_tile = [&](int b, int it) {
        const int k0 = (kit0 + it) * BK;
        const uint32_t dA = sA + (uint32_t)(b * STG_A) * 2;
        #pragma unroll
        for (int t = 0; t < 4; t++) {
            int g = tid + t * 256;
            int r = g >> 3, c = (g & 7) << 3;
            cp_async16(dA + (uint32_t)(r * LDA + c) * 2,
                       A + (size_t)(bm + r) * lda + k0 + c);
        }
        const uint32_t dB = sB + (uint32_t)(b * STG_B) * 2;
        if constexpr (BT) {
            #pragma unroll
            for (int t = 0; t < 4; t++) {
                int g = tid + t * 256;
                int r = g >> 3, c = (g & 7) << 3;
                cp_async16(dB + (uint32_t)(r * LDB + c) * 2,
                           B + (size_t)(bn + r) * ldb + k0 + c);
            }
        } else {
            #pragma unroll
            for (int t = 0; t < 4; t++) {
                int g = tid + t * 256;
                int r = g >> 4, c = (g & 15) << 3;
                cp_async16(dB + (uint32_t)(r * LDB + c) * 2,
                           B + (size_t)(k0 + r) * ldb + bn + c);
            }
        }
        CP_COMMIT();
    };

    wmma::fragment<wmma::accumulator, 16, 16, 16, float> acc[4][2];
    #pragma unroll
    for (int mi = 0; mi < 4; mi++)
        #pragma unroll
        for (int ni = 0; ni < 2; ni++)
            wmma::fill_fragment(acc[mi][ni], 0.0f);

    load_tile(0, 0);
    load_tile(1, 1);

    #pragma unroll 3
    for (int i = 0; i < nit; i++) {
        if (i + 1 < nit) { CP_WAIT1(); } else { CP_WAIT0(); }
        __syncthreads();
        if (i + 2 < nit) load_tile((i + 2) % 3, i + 2);

        const int s = i % 3;
        const __half* Ab = As + s * STG_A;
        const __half* Bb = Bs + s * STG_B;

        #pragma unroll
        for (int kk = 0; kk < BK; kk += 16) {
            wmma::fragment<wmma::matrix_a, 16, 16, 16, __half, wmma::row_major> af[4];
            #pragma unroll
            for (int mi = 0; mi < 4; mi++)
                wmma::load_matrix_sync(af[mi], Ab + (wm + mi * 16) * LDA + kk, LDA);

            if constexpr (BT) {
                wmma::fragment<wmma::matrix_b, 16, 16, 16, __half, wmma::col_major> bf[2];
                #pragma unroll
                for (int ni = 0; ni < 2; ni++)
                    wmma::load_matrix_sync(bf[ni], Bb + (wn + ni * 16) * LDB + kk, LDB);
                #pragma unroll
                for (int mi = 0; mi < 4; mi++)
                    #pragma unroll
                    for (int ni = 0; ni < 2; ni++)
                        wmma::mma_sync(acc[mi][ni], af[mi], bf[ni], acc[mi][ni]);
            } else {
                wmma::fragment<wmma::matrix_b, 16, 16, 16, __half, wmma::row_major> bf[2];
                #pragma unroll
                for (int ni = 0; ni < 2; ni++)
                    wmma::load_matrix_sync(bf[ni], Bb + kk * LDB + wn + ni * 16, LDB);
                #pragma unroll
                for (int mi = 0; mi < 4; mi++)
                    #pragma unroll
                    for (int ni = 0; ni < 2; ni++)
                        wmma::mma_sync(acc[mi][ni], af[mi], bf[ni], acc[mi][ni]);
            }
        }
    }

    if constexpr (EPI == 0) {
        float* C = (float*)Cv + (size_t)z * planeStride;
        #pragma unroll
        for (int mi = 0; mi < 4; mi++)
            #pragma unroll
            for (int ni = 0; ni < 2; ni++)
                wmma::store_matrix_sync(
                    C + (size_t)(bm + wm + mi * 16) * ldc + bn + wn + ni * 16,
                    acc[mi][ni], ldc, wmma::mem_row_major);
    } else {
        constexpr int LDC_S = 132;                       // floats
        float* Cs = (float*)smh;                         // 67584
        float* red = (float*)((char*)smh + 68608);       // 256 floats
        __syncthreads();
        #pragma unroll
        for (int mi = 0; mi < 4; mi++) {
            #pragma unroll
            for (int ni = 0; ni < 2; ni++) {
                if constexpr (EPI == 2) {
                    #pragma unroll
                    for (int e = 0; e < acc[mi][ni].num_elements; e++)
                        acc[mi][ni].x[e] = exp2f(acc[mi][ni].x[e]);
                }
                wmma::store_matrix_sync(Cs + (wm + mi * 16) * LDC_S + wn + ni * 16,
                                        acc[mi][ni], LDC_S, wmma::mem_row_major);
            }
        }
        __syncthreads();
        __half* C = (__half*)Cv;
        #pragma unroll
        for (int t = 0; t < 16; t++) {
            int g = tid + t * 256;
            int r = g >> 5, c = (g & 31) << 2;
            float4 v = *reinterpret_cast<const float4*>(Cs + r * LDC_S + c);
            __half2 h0 = __floats2half2_rn(v.x, v.y);
            __half2 h1 = __floats2half2_rn(v.z, v.w);
            uint2 u;
            u.x = *reinterpret_cast<uint32_t*>(&h0);
            u.y = *reinterpret_cast<uint32_t*>(&h1);
            *reinterpret_cast<uint2*>(C + (size_t)(bm + r) * ldc + bn + c) = u;
        }
        if constexpr (EPI == 2) {
            // per-block row sums (fp32 exp2 tile), all 256 threads: half-row each
            const int row  = tid & 127;
            const int half = tid >> 7;
            const float4* pr = reinterpret_cast<const float4*>(
                Cs + row * LDC_S + half * 64);
            float s = 0.0f;
            #pragma unroll
            for (int j = 0; j < 16; j++) {
                float4 v = pr[j];
                s += v.x + v.y + v.z + v.w;
            }
            red[tid] = s;
            __syncthreads();
            if (tid < 128)
                RS[(size_t)(bm + tid) * gridDim.x + blockIdx.x] =
                    red[tid] + red[tid + 128];
        }
    }
}

// ---------------------------------------------------------------------------
// N = alpha * Wk^T @ Wq  (TN, fp32 in, fp32 acc, fp16 out), 768x768.
// (alpha includes log2e so the score epilogue uses exp2.)
// Block 64x64, 128 thr = 4 warps (2x2), warp tile 32x32.
// ---------------------------------------------------------------------------
__global__ __launch_bounds__(128) void wkwq_tn(
    const float* __restrict__ wk, const float* __restrict__ wq,
    __half* __restrict__ Nout, float alpha)
{
    __shared__ __half Ta[64 * 72];     // [m][j]
    __shared__ __half Tb[64 * 72];     // [m][k]
    __shared__ float  Cs[64 * 68];

    const int tid  = threadIdx.x;
    const int warp = tid >> 5;
    const int j0   = blockIdx.y * 64;
    const int k0   = blockIdx.x * 64;
    const int wj   = (warp & 1) * 32;
    const int wk_  = (warp >> 1) * 32;

    wmma::fragment<wmma::accumulator, 16, 16, 16, float> acc[2][2];
    #pragma unroll
    for (int mi = 0; mi < 2; mi++)
        #pragma unroll
        for (int ni = 0; ni < 2; ni++)
            wmma::fill_fragment(acc[mi][ni], 0.0f);

    for (int m0 = 0; m0 < DIM; m0 += 64) {
        __syncthreads();
        #pragma unroll
        for (int e = 0; e < 8; e++) {
            int g = tid + e * 128;
            int r = g >> 4, c = (g & 15) << 2;
            float4 va = *reinterpret_cast<const float4*>(
                wk + (size_t)(m0 + r) * DIM + j0 + c);
            float4 vb = *reinterpret_cast<const float4*>(
                wq + (size_t)(m0 + r) * DIM + k0 + c);
            __half2 a0 = __floats2half2_rn(va.x, va.y);
            __half2 a1 = __floats2half2_rn(va.z, va.w);
            __half2 b0 = __floats2half2_rn(vb.x, vb.y);
            __half2 b1 = __floats2half2_rn(vb.z, vb.w);
            uint2 ua, ub;
            ua.x = *reinterpret_cast<uint32_t*>(&a0);
            ua.y = *reinterpret_cast<uint32_t*>(&a1);
            ub.x = *reinterpret_cast<uint32_t*>(&b0);
            ub.y = *reinterpret_cast<uint32_t*>(&b1);
            *reinterpret_cast<uint2*>(&Ta[r * 72 + c]) = ua;
            *reinterpret_cast<uint2*>(&Tb[r * 72 + c]) = ub;
        }
        __syncthreads();

        #pragma unroll
        for (int kk = 0; kk < 64; kk += 16) {
            wmma::fragment<wmma::matrix_a, 16, 16, 16, __half, wmma::col_major> af[2];
            wmma::fragment<wmma::matrix_b, 16, 16, 16, __half, wmma::row_major> bf[2];
            #pragma unroll
            for (int i = 0; i < 2; i++)
                wmma::load_matrix_sync(af[i], &Ta[kk * 72 + wj + i * 16], 72);
            #pragma unroll
            for (int i = 0; i < 2; i++)
                wmma::load_matrix_sync(bf[i], &Tb[kk * 72 + wk_ + i * 16], 72);
            #pragma unroll
            for (int mi = 0; mi < 2; mi++)
                #pragma unroll
                for (int ni = 0; ni < 2; ni++)
                    wmma::mma_sync(acc[mi][ni], af[mi], bf[ni], acc[mi][ni]);
        }
    }

    __syncthreads();
    #pragma unroll
    for (int mi = 0; mi < 2; mi++) {
        #pragma unroll
        for (int ni = 0; ni < 2; ni++) {
            #pragma unroll
            for (int e = 0; e < acc[mi][ni].num_elements; e++)
                acc[mi][ni].x[e] *= alpha;
            wmma::store_matrix_sync(Cs + (wj + mi * 16) * 68 + wk_ + ni * 16,
                                    acc[mi][ni], 68, wmma::mem_row_major);
        }
    }
    __syncthreads();
    #pragma unroll
    for (int e = 0; e < 8; e++) {
        int g = tid + e * 128;
        int r = g >> 4, c = (g & 15) << 2;
        float4 v = *reinterpret_cast<const float4*>(&Cs[r * 68 + c]);
        __half2 h0 = __floats2half2_rn(v.x, v.y);
        __half2 h1 = __floats2half2_rn(v.z, v.w);
        uint2 u;
        u.x = *reinterpret_cast<uint32_t*>(&h0);
        u.y = *reinterpret_cast<uint32_t*>(&h1);
        *reinterpret_cast<uint2*>(&Nout[(size_t)(j0 + r) * DIM + k0 + c]) = u;
    }
}

// ---------------- fused fp32 -> fp16 conversion (x, wv) ----------------
__global__ void __launch_bounds__(256) f2h_all(
    const float* __restrict__ x, const float* __restrict__ wv,
    __half* __restrict__ Xh, __half* __restrict__ Wv_dst)
{
    constexpr int NX = SEQ * DIM / 4;
    constexpr int NW = DIM * DIM / 4;
    int i = blockIdx.x * 256 + threadIdx.x;
    const float* src; __half* dst; int j;
    if (i < NX)           { src = x;  dst = Xh;     j = i; }
    else if (i < NX + NW) { src = wv; dst = Wv_dst; j = i - NX; }
    else return;
    float4 v = reinterpret_cast<const float4*>(src)[j];
    __half2 h0 = __floats2half2_rn(v.x, v.y);
    __half2 h1 = __floats2half2_rn(v.z, v.w);
    uint2 u;
    u.x = *reinterpret_cast<uint32_t*>(&h0);
    u.y = *reinterpret_cast<uint32_t*>(&h1);
    reinterpret_cast<uint2*>(dst)[j] = u;
}

// ---------------- fused: invL from RS partials + split-K reduce + normalize ----
__global__ void __launch_bounds__(256) reduce_norm_all(
    const float* __restrict__ part, const float* __restrict__ RS,
    float* __restrict__ out)
{
    constexpr int PLANE4 = SEQ * DIM / 4;
    __shared__ float sinv[8];

    const int row0 = blockIdx.x * 8;
    const int w    = threadIdx.x >> 5;
    const int lane = threadIdx.x & 31;

    const float* rs = RS + (size_t)(row0 + w) * 64;
    float s = rs[lane] + rs[lane + 32];
    #pragma unroll
    for (int off = 16; off > 0; off >>= 1)
        s += __shfl_down_sync(0xFFFFFFFF, s, off);
    if (lane == 0) sinv[w] = 1.0f / s;
    __syncthreads();

    const float4* p = reinterpret_cast<const float4*>(part);
    float4* o = reinterpret_cast<float4*>(out);
    #pragma unroll
    for (int k = 0; k < 6; k++) {
        int i = threadIdx.x + k * 256;
        int r = i / 192;
        size_t idx = (size_t)(row0) * 192 + i;
        const float sv = sinv[r];
        float4 a = p[idx];
        float4 b = p[idx + PLANE4];
        float4 c = p[idx + 2 * PLANE4];
        float4 v;
        v.x = (a.x + b.x + c.x) * sv;
        v.y = (a.y + b.y + c.y) * sv;
        v.z = (a.z + b.z + c.z) * sv;
        v.w = (a.w + b.w + c.w) * sv;
        o[idx] = v;
    }
}

// ---------------- launch ----------------
extern "C" void kernel_launch(void* const* d_in, const int* in_sizes, int n_in,
                              void* d_out, int out_size)
{
    const float* x  = (const float*)d_in[0];
    const float* wq = (const float*)d_in[1];
    const float* wk = (const float*)d_in[2];
    const float* wv = (const float*)d_in[3];
    float* out = (float*)d_out;

    __half *Xh, *Wc2, *QVh, *P;
    float *RS, *Part;
    cudaGetSymbolAddress((void**)&Xh,  g_Xh);
    cudaGetSymbolAddress((void**)&Wc2, g_Wc2);
    cudaGetSymbolAddress((void**)&QVh, g_QVh);
    cudaGetSymbolAddress((void**)&P,   g_P);
    cudaGetSymbolAddress((void**)&RS,  g_RS);
    cudaGetSymbolAddress((void**)&Part, g_Part);

    constexpr int SM_NT = 3 * (STG_A + BN * 72) * 2;    // 110592
    constexpr int SM_NN = 3 * (STG_A + BK * 136) * 2;   // 107520
    cudaFuncSetAttribute((const void*)gemm_h<1, true>,
                         cudaFuncAttributeMaxDynamicSharedMemorySize, SM_NT);
    cudaFuncSetAttribute((const void*)gemm_h<2, true>,
                         cudaFuncAttributeMaxDynamicSharedMemorySize, SM_NT);
    cudaFuncSetAttribute((const void*)gemm_h<0, false>,
                         cudaFuncAttributeMaxDynamicSharedMemorySize, SM_NN);

    dim3 blk(256);
    const float alpha = 1.44269504088896f / sqrtf((float)DIM);   // log2e folded

    // (1) fp32 -> fp16 for x; wv -> Wc2 rows [768,1536)
    constexpr int N4 = (SEQ * DIM + DIM * DIM) / 4;
    f2h_all<<<(N4 + 255) / 256, 256>>>(x, wv, Xh, Wc2 + (size_t)DIM * DIM);

    // (2) N = (alpha*log2e) * Wk^T @ Wq -> Wc2 rows [0,768)
    wkwq_tn<<<dim3(DIM / 64, DIM / 64), 128>>>(wk, wq, Wc2, alpha);

    // (3) projection (NT): QV = Xh @ Wc2^T -> [q' | v], fp16
    dim3 gProj(QV2 / BN, SEQ / BM);                  // 12 x 64
    gemm_h<1, true><<<gProj, blk, SM_NT>>>(
        Xh, DIM, Wc2, DIM, QVh, QV2, DIM / BK, DIM / BK, 0, nullptr);

    // (4) P = exp2(Q' @ Xh^T) (NT), fp16, + per-block row sums
    dim3 gScore(SEQ / BN, SEQ / BM);                 // 64 x 64
    gemm_h<2, true><<<gScore, blk, SM_NT>>>(
        QVh, QV2, Xh, DIM, P, SEQ, DIM / BK, DIM / BK, 0, RS);

    // (5) PV (NN, B = V slice of QVh) split-K=3 partials
    dim3 gPV(DIM / BN, SEQ / BM, 3);                 // 6 x 64 x 3
    gemm_h<0, false><<<gPV, blk, SM_NN>>>(
        P, SEQ, QVh + DIM, QV2, Part, DIM, SEQ / BK, 43,
        (size_t)SEQ * DIM, nullptr);

    // (6) out = (sum of split-K partials) / rowsum
    reduce_norm_all<<<SEQ / 8, 256>>>(Part, RS, out);
}